// round 13
// baseline (speedup 1.0000x reference)
#include <cuda_runtime.h>
#include <mma.h>
#include <cstdint>

using namespace nvcuda;

#define NP 256
#define NG 1024
#define F  128
#define EPSV 1e-5f

#define BP 32      // probes per block  (M = 64 rows = 32p x 2c interleaved)
#define BN 64      // gallery per block
#define KC 16      // K-chunk (8 chunks)
#define THREADS 256
#define LDT 20     // hi/lo tile row stride (floats)
#define LDC 68     // cross spill row stride (floats)

typedef wmma::fragment<wmma::matrix_a, 16, 16, 8, wmma::precision::tf32, wmma::row_major> FragA;
typedef wmma::fragment<wmma::matrix_b, 16, 16, 8, wmma::precision::tf32, wmma::col_major> FragB;
typedef wmma::fragment<wmma::accumulator, 16, 16, 8, float> FragC;

// carve one buffer: hi/lo tiles during mainloop, cross spill in epilogue
#define A_HI 0
#define A_LO (A_HI + 64 * LDT)          // 1280
#define G_HI (A_LO + 64 * LDT)          // 2560
#define G_LO (G_HI + 64 * LDT)          // 3840
#define BUF_FLOATS (G_LO + 64 * LDT)    // 5120 floats = 20 KB  (>= 64*LDC=4352 spill)

__device__ __forceinline__ void split1(float v, float& hi, float& lo) {
    hi = wmma::__float_to_tf32(v);
    lo = wmma::__float_to_tf32(v - hi);
}

// out[p,g,c] = A2[p,c] + B2[g,c] + K[c] - 2 * sum_f (p_f w'_cf) g_f
// Tensor-core cross term; tf32 hi/lo split HOISTED to the load phase.
__global__ void __launch_bounds__(THREADS) cls_kernel(
    const float* __restrict__ probe, const float* __restrict__ gal,
    const float* __restrict__ bnw, const float* __restrict__ bnb,
    const float* __restrict__ bnm, const float* __restrict__ bnv,
    const float* __restrict__ W, const float* __restrict__ bias,
    float* __restrict__ out)
{
    __shared__ __align__(16) float BUF[BUF_FLOATS];
    __shared__ __align__(16) float sW0[F];
    __shared__ __align__(16) float sW1[F];
    __shared__ float sA2c[2][BP];
    __shared__ float2 sB2[BN];
    __shared__ float2 sK4[4];

    const int tid  = threadIdx.x;
    const int lane = tid & 31;
    const int warp = tid >> 5;       // 0..7
    const int bp = blockIdx.y * BP;
    const int bg = blockIdx.x * BN;

    // -------- folded weights + K reduction (threads 0..127) --------
    if (tid < F) {
        const int f = tid;
        const float inv = bnw[f] * rsqrtf(bnv[f] + EPSV);
        const float Wf0 = W[f], Wf1 = W[F + f];
        sW0[f] = Wf0 * inv;
        sW1[f] = Wf1 * inv;
        const float off = bnb[f] - bnm[f] * inv;
        float k0 = Wf0 * off, k1 = Wf1 * off;
        for (int o = 16; o > 0; o >>= 1) {
            k0 += __shfl_down_sync(0xffffffffu, k0, o);
            k1 += __shfl_down_sync(0xffffffffu, k1, o);
        }
        if (lane == 0)
            sK4[warp] = make_float2(k0 + (warp == 0 ? bias[0] : 0.f),
                                    k1 + (warp == 0 ? bias[1] : 0.f));
    }

    // load mappings (fixed across chunks)
    const int pA = tid >> 3;               // probe row 0..31
    const int ciA = (tid >> 2) & 1;        // class 0/1
    const int qA = tid & 3;                // col quad within chunk
    const int gG = tid >> 2;               // gallery row 0..63
    const int qG = tid & 3;

    float paAcc = 0.f;                     // diag partial for (pA, ciA)
    float gb0 = 0.f, gb1 = 0.f;            // diag partials for gG

    const int mw = warp & 3;               // m-tile 16*mw
    const int nw = warp >> 2;              // n-half 32*nw
    FragC acc[2];
    wmma::fill_fragment(acc[0], 0.f);
    wmma::fill_fragment(acc[1], 0.f);

    for (int kc = 0; kc < F; kc += KC) {
        __syncthreads();   // protect BUF from prior chunk's MMA reads (also covers sW init)

        // ---- A: one float4 per thread -> scaled, split, stored hi/lo ----
        {
            const int col = 4 * qA;
            const float4 x = *(const float4*)(probe + (size_t)(bp + pA) * F + kc + col);
            const float4 w = ciA ? *(const float4*)&sW1[kc + col]
                                 : *(const float4*)&sW0[kc + col];
            float4 a, hi, lo;
            a.x = x.x * w.x; a.y = x.y * w.y; a.z = x.z * w.z; a.w = x.w * w.w;
            split1(a.x, hi.x, lo.x); split1(a.y, hi.y, lo.y);
            split1(a.z, hi.z, lo.z); split1(a.w, hi.w, lo.w);
            const int row = 2 * pA + ciA;
            *(float4*)&BUF[A_HI + row * LDT + col] = hi;
            *(float4*)&BUF[A_LO + row * LDT + col] = lo;
            paAcc += a.x * x.x + a.y * x.y + a.z * x.z + a.w * x.w;
        }
        // ---- G: one float4 per thread -> split, stored hi/lo ----
        {
            const int col = 4 * qG;
            const float4 x = *(const float4*)(gal + (size_t)(bg + gG) * F + kc + col);
            const float4 w0 = *(const float4*)&sW0[kc + col];
            const float4 w1 = *(const float4*)&sW1[kc + col];
            float4 hi, lo;
            split1(x.x, hi.x, lo.x); split1(x.y, hi.y, lo.y);
            split1(x.z, hi.z, lo.z); split1(x.w, hi.w, lo.w);
            *(float4*)&BUF[G_HI + gG * LDT + col] = hi;
            *(float4*)&BUF[G_LO + gG * LDT + col] = lo;
            const float xx = x.x * x.x, yy = x.y * x.y, zz = x.z * x.z, ww = x.w * x.w;
            gb0 += w0.x * xx + w0.y * yy + w0.z * zz + w0.w * ww;
            gb1 += w1.x * xx + w1.y * yy + w1.z * zz + w1.w * ww;
        }
        __syncthreads();

        // ---- pure-MMA mainloop: 2 s-steps x (A loads + 2 n-tiles x (B loads + 3 mma)) ----
        for (int s = 0; s < 2; s++) {
            FragA a_hi, a_lo;
            wmma::load_matrix_sync(a_hi, &BUF[A_HI + (16 * mw) * LDT + 8 * s], LDT);
            wmma::load_matrix_sync(a_lo, &BUF[A_LO + (16 * mw) * LDT + 8 * s], LDT);
            for (int t2 = 0; t2 < 2; t2++) {
                const int gr = 32 * nw + 16 * t2;
                FragB b_hi, b_lo;
                wmma::load_matrix_sync(b_hi, &BUF[G_HI + gr * LDT + 8 * s], LDT);
                wmma::load_matrix_sync(b_lo, &BUF[G_LO + gr * LDT + 8 * s], LDT);
                wmma::mma_sync(acc[t2], a_hi, b_hi, acc[t2]);
                wmma::mma_sync(acc[t2], a_hi, b_lo, acc[t2]);
                wmma::mma_sync(acc[t2], a_lo, b_hi, acc[t2]);
            }
        }
    }

    // -------- one-time diag reductions --------
    paAcc += __shfl_down_sync(0xffffffffu, paAcc, 2, 4);
    paAcc += __shfl_down_sync(0xffffffffu, paAcc, 1, 4);
    if (qA == 0) sA2c[ciA][pA] = paAcc;
    gb0 += __shfl_down_sync(0xffffffffu, gb0, 2, 4);
    gb0 += __shfl_down_sync(0xffffffffu, gb0, 1, 4);
    gb1 += __shfl_down_sync(0xffffffffu, gb1, 2, 4);
    gb1 += __shfl_down_sync(0xffffffffu, gb1, 1, 4);
    if (qG == 0) sB2[gG] = make_float2(gb0, gb1);

    __syncthreads();   // MMA reads done; BUF becomes cross-spill scratch

    wmma::store_matrix_sync(&BUF[(16 * mw) * LDC + 32 * nw], acc[0], LDC, wmma::mem_row_major);
    wmma::store_matrix_sync(&BUF[(16 * mw) * LDC + 32 * nw + 16], acc[1], LDC, wmma::mem_row_major);
    __syncthreads();

    // -------- epilogue: 16 outputs per thread --------
    const float2 K01 = make_float2(sK4[0].x + sK4[1].x + sK4[2].x + sK4[3].x,
                                   sK4[0].y + sK4[1].y + sK4[2].y + sK4[3].y);
    {
        const int i  = tid >> 3;            // probe 0..31
        const int gg = (tid & 7) * 8;       // gallery 0..56 step 8
        const float ax = sA2c[0][i] + K01.x;
        const float ay = sA2c[1][i] + K01.y;
        float* dst = out + ((size_t)(bp + i) * NG + bg + gg) * 2;
        #pragma unroll
        for (int half = 0; half < 2; half++) {
            const float4 c0 = *(const float4*)&BUF[(2 * i)     * LDC + gg + 4 * half];
            const float4 c1 = *(const float4*)&BUF[(2 * i + 1) * LDC + gg + 4 * half];
            const float2 b0 = sB2[gg + 4 * half];
            const float2 b1 = sB2[gg + 4 * half + 1];
            const float2 b2 = sB2[gg + 4 * half + 2];
            const float2 b3 = sB2[gg + 4 * half + 3];
            float4 o0, o1;
            o0.x = fmaf(-2.0f, c0.x, ax + b0.x);
            o0.y = fmaf(-2.0f, c1.x, ay + b0.y);
            o0.z = fmaf(-2.0f, c0.y, ax + b1.x);
            o0.w = fmaf(-2.0f, c1.y, ay + b1.y);
            o1.x = fmaf(-2.0f, c0.z, ax + b2.x);
            o1.y = fmaf(-2.0f, c1.z, ay + b2.y);
            o1.z = fmaf(-2.0f, c0.w, ax + b3.x);
            o1.w = fmaf(-2.0f, c1.w, ay + b3.y);
            ((float4*)dst)[2 * half]     = o0;
            ((float4*)dst)[2 * half + 1] = o1;
        }
    }
}

// ---------------- launch: ONE kernel, best-observed grid shape ----------------
extern "C" void kernel_launch(void* const* d_in, const int* in_sizes, int n_in,
                              void* d_out, int out_size) {
    const float* probe = (const float*)d_in[0];
    const float* gal   = (const float*)d_in[1];
    const float* bnw   = (const float*)d_in[2];
    const float* bnb   = (const float*)d_in[3];
    const float* bnm   = (const float*)d_in[4];
    const float* bnv   = (const float*)d_in[5];
    const float* W     = (const float*)d_in[6];
    const float* bias  = (const float*)d_in[7];
    float* out = (float*)d_out;

    dim3 grid(NG / BN, NP / BP);   // (16, 8) = 128 blocks x 256 threads
    cls_kernel<<<grid, THREADS>>>(probe, gal, bnw, bnb, bnm, bnv, W, bias, out);
}

// round 14
// speedup vs baseline: 1.5158x; 1.5158x over previous
#include <cuda_runtime.h>
#include <cstdint>

#define NP 256
#define NG 1024
#define F  128
#define EPSV 1e-5f

#define TP 32
#define TG 64
#define KC 64

// ---------------- f32x2 helpers ----------------
__device__ __forceinline__ unsigned long long fma2(unsigned long long a,
                                                   unsigned long long b,
                                                   unsigned long long c) {
    unsigned long long d;
    asm("fma.rn.f32x2 %0, %1, %2, %3;" : "=l"(d) : "l"(a), "l"(b), "l"(c));
    return d;
}
__device__ __forceinline__ unsigned long long dup2(float x) {
    unsigned long long d;
    asm("mov.b64 %0, {%1, %1};" : "=l"(d) : "f"(x));
    return d;
}
__device__ __forceinline__ float2 unpack2(unsigned long long v) {
    float2 r;
    asm("mov.b64 {%0, %1}, %2;" : "=f"(r.x), "=f"(r.y) : "l"(v));
    return r;
}

// ---------------- single fused kernel (R6 + full LDG prefetch) ----------------
// out[p,g,c] = A[p,c] + B[g,c] + K[c] - 2 * sum_f (p_f * w'_cf) * g_f
__global__ void __launch_bounds__(256) cls_kernel(
    const float* __restrict__ probe, const float* __restrict__ gal,
    const float* __restrict__ bnw, const float* __restrict__ bnb,
    const float* __restrict__ bnm, const float* __restrict__ bnv,
    const float* __restrict__ W, const float* __restrict__ bias,
    float* __restrict__ out)
{
    __shared__ __align__(16) float2 sP[KC + 1][TP + 1];  // stride 264 B; 8B reads only
    __shared__ __align__(16) float  sG[KC + 1][TG + 4];  // stride 272 B; float4 reads
    __shared__ float2 sA[TP];
    __shared__ float2 sB[TG];

    const int tid  = threadIdx.x;
    const int lane = tid & 31;
    const int warp = tid >> 5;
    const int bp = blockIdx.y * TP;
    const int bg = blockIdx.x * TG;

    // ======== PREFETCH: all 48 global data loads issued up-front (MLP ~48), ========
    // their DRAM latency overlaps the weight-fold prologue below.
    float px[2][4][2];   // [chunk][k][half]: probe rows p = warp + 8k
    float gx[2][8][2];   // [chunk][k][half]: gallery rows g = warp + 8k
    #pragma unroll
    for (int c = 0; c < 2; c++) {
        #pragma unroll
        for (int k = 0; k < 4; k++) {
            const float* src = probe + (size_t)(bp + warp + 8 * k) * F + c * KC;
            px[c][k][0] = src[lane];
            px[c][k][1] = src[lane + 32];
        }
        #pragma unroll
        for (int k = 0; k < 8; k++) {
            const float* src = gal + (size_t)(bg + warp + 8 * k) * F + c * KC;
            gx[c][k][0] = src[lane];
            gx[c][k][1] = src[lane + 32];
        }
    }

    // -------- folded weights (lane f-stripe) + K reduction --------
    float w0r[4], w1r[4];
    float kc0 = 0.f, kc1 = 0.f;
    #pragma unroll
    for (int i = 0; i < 4; i++) {
        const int f = lane + 32 * i;
        const float inv = bnw[f] * rsqrtf(bnv[f] + EPSV);
        const float Wf0 = W[f], Wf1 = W[F + f];
        w0r[i] = Wf0 * inv;
        w1r[i] = Wf1 * inv;
        const float off = bnb[f] - bnm[f] * inv;
        kc0 = fmaf(Wf0, off, kc0);
        kc1 = fmaf(Wf1, off, kc1);
    }
    #pragma unroll
    for (int o = 16; o > 0; o >>= 1) {
        kc0 += __shfl_xor_sync(0xffffffffu, kc0, o);
        kc1 += __shfl_xor_sync(0xffffffffu, kc1, o);
    }
    kc0 += bias[0];
    kc1 += bias[1];

    // -------- thread mapping: 2 probes x 4 gallery x 2 classes --------
    const int ty = tid >> 4, tx = tid & 15;
    const int tp = 2 * ty, tg = 4 * tx;

    unsigned long long a00 = 0, a01 = 0, a02 = 0, a03 = 0;
    unsigned long long a10 = 0, a11 = 0, a12 = 0, a13 = 0;

    float pa0[4], pa1[4];
    float gb0[8], gb1[8];
    #pragma unroll
    for (int k = 0; k < 4; k++) { pa0[k] = 0.f; pa1[k] = 0.f; }
    #pragma unroll
    for (int k = 0; k < 8; k++) { gb0[k] = 0.f; gb1[k] = 0.f; }

    #pragma unroll
    for (int c = 0; c < 2; c++) {
        // ---- scale + store probes from REGISTERS (no LDG here) ----
        #pragma unroll
        for (int k = 0; k < 4; k++) {
            const int p = warp + 8 * k;
            const float x0 = px[c][k][0];
            const float x1 = px[c][k][1];
            const float s00 = x0 * w0r[2 * c],     s01 = x0 * w1r[2 * c];
            const float s10 = x1 * w0r[2 * c + 1], s11 = x1 * w1r[2 * c + 1];
            sP[lane][p]      = make_float2(s00, s01);
            sP[lane + 32][p] = make_float2(s10, s11);
            pa0[k] = fmaf(s00, x0, fmaf(s10, x1, pa0[k]));
            pa1[k] = fmaf(s01, x0, fmaf(s11, x1, pa1[k]));
        }
        // ---- store gallery from REGISTERS ----
        #pragma unroll
        for (int k = 0; k < 8; k++) {
            const int g = warp + 8 * k;
            const float x0 = gx[c][k][0];
            const float x1 = gx[c][k][1];
            sG[lane][g]      = x0;
            sG[lane + 32][g] = x1;
            gb0[k] = fmaf(w0r[2 * c] * x0, x0, fmaf(w0r[2 * c + 1] * x1, x1, gb0[k]));
            gb1[k] = fmaf(w1r[2 * c] * x0, x0, fmaf(w1r[2 * c + 1] * x1, x1, gb1[k]));
        }
        __syncthreads();

        // ---- FMA mainloop; sP via two aligned 8B loads ----
        unsigned long long Pv0 = *(const unsigned long long*)&sP[0][tp];
        unsigned long long Pv1 = *(const unsigned long long*)&sP[0][tp + 1];
        float4 Gv = *(const float4*)&sG[0][tg];
        #pragma unroll 8
        for (int f = 0; f < KC; f++) {
            const unsigned long long P0n = *(const unsigned long long*)&sP[f + 1][tp];
            const unsigned long long P1n = *(const unsigned long long*)&sP[f + 1][tp + 1];
            const float4 Gn = *(const float4*)&sG[f + 1][tg];
            const unsigned long long g0 = dup2(Gv.x);
            const unsigned long long g1 = dup2(Gv.y);
            const unsigned long long g2 = dup2(Gv.z);
            const unsigned long long g3 = dup2(Gv.w);
            a00 = fma2(Pv0, g0, a00);
            a01 = fma2(Pv0, g1, a01);
            a02 = fma2(Pv0, g2, a02);
            a03 = fma2(Pv0, g3, a03);
            a10 = fma2(Pv1, g0, a10);
            a11 = fma2(Pv1, g1, a11);
            a12 = fma2(Pv1, g2, a12);
            a13 = fma2(Pv1, g3, a13);
            Pv0 = P0n; Pv1 = P1n; Gv = Gn;
        }
        __syncthreads();
    }

    // -------- reduce A/B partials across lanes into smem --------
    #pragma unroll
    for (int k = 0; k < 4; k++) {
        float r0 = pa0[k], r1 = pa1[k];
        #pragma unroll
        for (int o = 16; o > 0; o >>= 1) {
            r0 += __shfl_down_sync(0xffffffffu, r0, o);
            r1 += __shfl_down_sync(0xffffffffu, r1, o);
        }
        if (lane == 0) sA[warp + 8 * k] = make_float2(r0, r1);
    }
    #pragma unroll
    for (int k = 0; k < 8; k++) {
        float r0 = gb0[k], r1 = gb1[k];
        #pragma unroll
        for (int o = 16; o > 0; o >>= 1) {
            r0 += __shfl_down_sync(0xffffffffu, r0, o);
            r1 += __shfl_down_sync(0xffffffffu, r1, o);
        }
        if (lane == 0) sB[warp + 8 * k] = make_float2(r0, r1);
    }
    __syncthreads();

    // -------- epilogue --------
    float2 Bv[4];
    #pragma unroll
    for (int j = 0; j < 4; j++) Bv[j] = sB[tg + j];

    #pragma unroll
    for (int i = 0; i < 2; i++) {
        const float2 Ap = sA[tp + i];
        const float ax = Ap.x + kc0;
        const float ay = Ap.y + kc1;
        const float2 u0 = unpack2(i == 0 ? a00 : a10);
        const float2 u1 = unpack2(i == 0 ? a01 : a11);
        const float2 u2 = unpack2(i == 0 ? a02 : a12);
        const float2 u3 = unpack2(i == 0 ? a03 : a13);
        float4 v0, v1;
        v0.x = fmaf(-2.0f, u0.x, ax + Bv[0].x);
        v0.y = fmaf(-2.0f, u0.y, ay + Bv[0].y);
        v0.z = fmaf(-2.0f, u1.x, ax + Bv[1].x);
        v0.w = fmaf(-2.0f, u1.y, ay + Bv[1].y);
        v1.x = fmaf(-2.0f, u2.x, ax + Bv[2].x);
        v1.y = fmaf(-2.0f, u2.y, ay + Bv[2].y);
        v1.z = fmaf(-2.0f, u3.x, ax + Bv[3].x);
        v1.w = fmaf(-2.0f, u3.y, ay + Bv[3].y);
        float4* dst = (float4*)(out + ((size_t)(bp + tp + i) * NG + bg + tg) * 2);
        dst[0] = v0;
        dst[1] = v1;
    }
}

// ---------------- launch: ONE kernel ----------------
extern "C" void kernel_launch(void* const* d_in, const int* in_sizes, int n_in,
                              void* d_out, int out_size) {
    const float* probe = (const float*)d_in[0];
    const float* gal   = (const float*)d_in[1];
    const float* bnw   = (const float*)d_in[2];
    const float* bnb   = (const float*)d_in[3];
    const float* bnm   = (const float*)d_in[4];
    const float* bnv   = (const float*)d_in[5];
    const float* W     = (const float*)d_in[6];
    const float* bias  = (const float*)d_in[7];
    float* out = (float*)d_out;

    dim3 grid(NG / TG, NP / TP);   // (16, 8) = 128 blocks x 256 threads
    cls_kernel<<<grid, 256>>>(probe, gal, bnw, bnb, bnm, bnv, W, bias, out);
}